// round 11
// baseline (speedup 1.0000x reference)
#include <cuda_runtime.h>
#include <cstdint>
#include <math.h>

#define S_LEN 512
#define BATCH 256
#define IN    256
#define HID   1024
#define SWID  256
#define SDEP  100
#define KTOT  1536
#define IS    (IN + SWID)     // 512
#define NB    128
#define NT    256

#define BUFSZ  4224           // A frag buffer per stage: 4 mf * 8 ks * 132
#define BBASE  (2 * BUFSZ)    // float offset of B ring
#define DYNSM  ((2 * BUFSZ + 3 * 8192) * 4)   // 132096 bytes

// ---------------- scratch (no allocations allowed) ----------------
__device__ __align__(16) float g_stackA[BATCH * SDEP * SWID];   // 26.2 MB
__device__ __align__(16) float g_stackB[BATCH * SDEP * SWID];   // 26.2 MB (also prep staging)
__device__ __align__(16) float g_Wf[32 * 48 * 4096];            // 25.2 MB tile-ordered weights
__device__ __align__(16) float g_bias[4 * HID];
__device__ __align__(16) float g_c[BATCH * HID];
__device__ __align__(16) float g_d[2 * BATCH * SWID];
__device__ float g_ctl[2 * BATCH * 3];
__device__ unsigned g_cnt;
__device__ volatile unsigned g_gen;

// ---------------- helpers ----------------
__device__ __forceinline__ float ftf32(float x) {
    float y;
    asm("cvt.rna.tf32.f32 %0, %1;" : "=f"(y) : "f"(x));
    return y;
}
__device__ __forceinline__ uint32_t smem_u32(const void* p) {
    uint32_t a;
    asm("{ .reg .u64 t; cvta.to.shared.u64 t, %1; cvt.u32.u64 %0, t; }" : "=r"(a) : "l"(p));
    return a;
}
__device__ __forceinline__ void cpa16(uint32_t dst, const void* src) {
    asm volatile("cp.async.cg.shared.global [%0], [%1], 16;" :: "r"(dst), "l"(src) : "memory");
}
__device__ __forceinline__ void cpa_commit() { asm volatile("cp.async.commit_group;" ::: "memory"); }
template <int N> __device__ __forceinline__ void cpa_wait() {
    asm volatile("cp.async.wait_group %0;" :: "n"(N) : "memory");
}

__device__ __forceinline__ void mma_tf32(float c[4], const uint32_t a[4], const uint32_t b[2]) {
    asm volatile(
        "mma.sync.aligned.m16n8k8.row.col.f32.tf32.tf32.f32 "
        "{%0,%1,%2,%3}, {%4,%5,%6,%7}, {%8,%9}, {%0,%1,%2,%3};\n"
        : "+f"(c[0]), "+f"(c[1]), "+f"(c[2]), "+f"(c[3])
        : "r"(a[0]), "r"(a[1]), "r"(a[2]), "r"(a[3]), "r"(b[0]), "r"(b[1]));
}

// ---------------- software grid barrier ----------------
__device__ __forceinline__ void bar_arrive(unsigned* myGen) {
    __syncthreads();
    if (threadIdx.x == 0) {
        unsigned my = g_gen;
        __threadfence();
        unsigned a = atomicAdd(&g_cnt, 1u);
        if (a == NB - 1) {
            g_cnt = 0;
            __threadfence();
            g_gen = my + 1;
        }
        *myGen = my;
    }
}
__device__ __forceinline__ void bar_wait(unsigned myGen) {
    if (threadIdx.x == 0) {
        while (g_gen == myGen) { }
        __threadfence();
    }
    __syncthreads();
}
__device__ __forceinline__ void gbar() {
    unsigned m;
    bar_arrive(&m);
    bar_wait(m);
}

// ---------------- stack blend ----------------
__device__ __forceinline__ void blend_range(
    const float* __restrict__ Sp, float* __restrict__ So,
    const float* __restrict__ dbuf, const float* __restrict__ ctlbuf,
    int is_t0, int bid, int tid)
{
    const float4* sin4  = (const float4*)Sp;
    float4*       sout4 = (float4*)So;
    const float4* d4    = (const float4*)dbuf;
    const int per_blk = (BATCH * SDEP * (SWID / 4)) / NB;   // 12800
    for (int ii = tid; ii < per_blk; ii += NT) {
        const int idx = bid * per_blk + ii;
        const int w4   = idx & 63;
        const int jrow = (idx >> 6) % SDEP;
        const int b    = idx / (SDEP * 64);
        const int base = b * SDEP * 64;
        float4 cur = sin4[base + jrow * 64 + w4];
        float4 o;
        if (is_t0) {
            o = cur;
        } else {
            const float pu = ctlbuf[b * 3 + 0];
            const float po = ctlbuf[b * 3 + 1];
            const float nn = ctlbuf[b * 3 + 2];
            float4 up = (jrow == 0) ? d4[b * 64 + w4] : sin4[base + (jrow - 1) * 64 + w4];
            float4 dn = make_float4(0.f, 0.f, 0.f, 0.f);
            if (jrow < SDEP - 1) dn = sin4[base + (jrow + 1) * 64 + w4];
            o.x = nn * cur.x + pu * up.x + po * dn.x;
            o.y = nn * cur.y + pu * up.y + po * dn.y;
            o.z = nn * cur.z + pu * up.z + po * dn.z;
            o.w = nn * cur.w + pu * up.w + po * dn.w;
        }
        sout4[idx] = o;
    }
}

// ---------------- the persistent kernel (prep + 512 steps) ----------------
__global__ __launch_bounds__(NT) void stackrnn_persistent(
    const float* __restrict__ x,      // [S, B, IN]
    const float* __restrict__ h0,
    const float* __restrict__ W_ih,   // [4H, IS]
    const float* __restrict__ W_hh,   // [4H, H]
    const float* __restrict__ b_ih,
    const float* __restrict__ b_hh,
    const float* __restrict__ A_w,
    const float* __restrict__ A_b,
    const float* __restrict__ D_w,
    const float* __restrict__ D_b,
    float* __restrict__ outs,         // [S, B, H]
    float* __restrict__ stackn)       // [B, SDEP, SWID]
{
    extern __shared__ __align__(16) float sm[];   // [0,2*BUFSZ) A frags, [BBASE,+3*8192) B ring

    const int bid = blockIdx.x;
    const int tid = threadIdx.x;
    const int warp = tid >> 5, lane = tid & 31;
    const int wm = warp >> 2, wn = warp & 3;        // 2m x 4n warps, warp tile 32x32
    const int gi_r = lane >> 2, tig = lane & 3;
    const int jt = bid & 31, mt = bid >> 5, bm0 = mt * 64;
    const int j0 = jt * 32;

    // ======== prep P1: plain tf32 weights -> g_stackB, fused bias ========
    for (int idx = bid * NT + tid; idx < 4 * HID * KTOT; idx += NB * NT) {
        int row = idx / KTOT, k = idx - row * KTOT;
        float v = (k < IS) ? W_ih[(size_t)row * IS + k]
                           : W_hh[(size_t)row * HID + (k - IS)];
        g_stackB[idx] = ftf32(v);
    }
    for (int i = bid * NT + tid; i < 4 * HID; i += NB * NT)
        g_bias[i] = b_ih[i] + b_hh[i];
    gbar();
    // ======== prep P2: tile-order swizzle -> g_Wf ========
    // granule (jt, kc32): [wnn(4)]*1024 + [g(4)]*256 + [ln(32)]*8 + [w(8)]; w = ks*2+p
    for (int idx = bid * NT + tid; idx < 32 * 48 * 4096; idx += NB * NT) {
        int w    = idx & 7;
        int ln   = (idx >> 3) & 31;
        int g    = (idx >> 8) & 3;
        int wnn  = (idx >> 10) & 3;
        int kc   = (idx >> 12) % 48;
        int jtt  = idx / (48 * 4096);
        int row = g * HID + jtt * 32 + wnn * 8 + (ln >> 2);
        int k   = kc * 32 + (w >> 1) * 8 + (ln & 3) + 4 * (w & 1);
        g_Wf[idx] = g_stackB[(size_t)row * KTOT + k];
    }
    gbar();

    // A loader role: thread -> row lr (0..63), k byte-lane lq (0..3)
    const int lr = tid >> 2;            // 0..63
    const int lq = tid & 3;             // 0..3 ; lk = lq*8
    const int lk = lq << 3;
    const int lb = bm0 + lr;
    // frag-scatter constants
    const int s_mf = lr >> 4;
    const int s_r  = lr & 15;
    const int s_base = (s_mf * 8) * 132 + (s_r & 7) * 16 + (s_r >> 3);
    // B fill/read bases
    const uint32_t smem_base = smem_u32(sm);
    const uint32_t bfill_dst = smem_base + BBASE * 4 + tid * 128;   // 32 floats/thread
    const float*   bsrc_base = g_Wf + (size_t)jt * 48 * 4096 + tid * 32;
    const float*   brd_base  = sm + BBASE;

    for (int t = 0; t < S_LEN; t++) {
        const float* x_t    = x + (size_t)t * BATCH * IN;
        const float* h_prev = t ? outs + (size_t)(t - 1) * BATCH * HID : h0;
        float*       h_out  = outs + (size_t)t * BATCH * HID;
        const float* Sp = (t & 1) ? g_stackB : g_stackA;
        float*       So = (t & 1) ? g_stackA : g_stackB;
        const float* dprev   = g_d   + ((t + 1) & 1) * (BATCH * SWID);
        const float* ctlprev = g_ctl + ((t + 1) & 1) * (BATCH * 3);
        float*       dcur    = g_d   + (t & 1) * (BATCH * SWID);
        float*       ctlcur  = g_ctl + (t & 1) * (BATCH * 3);

        float cpu = 0.f, cpo = 0.f, cnn = 1.f;
        if (t) {
            cpu = ctlprev[lb * 3 + 0];
            cpo = ctlprev[lb * 3 + 1];
            cnn = ctlprev[lb * 3 + 2];
        }
        const float* pX = x_t + (size_t)lb * IN;
        const float* pS = Sp + (size_t)lb * (SDEP * SWID) - IN;
        const float* pD = dprev + (size_t)lb * SWID - IN;
        const float* pH = h_prev + (size_t)lb * HID - IS;

        // kc64 regions: x = kc 0..3, stack = kc 4..7, h = kc 8..23
        auto ldgA = [&](int kc, float4 v[4]) {
#pragma unroll
            for (int hh = 0; hh < 2; hh++) {
                const int kk = kc * 64 + hh * 32 + lk;
                if (kk < IN) {
                    v[hh * 2 + 0] = *(const float4*)(pX + kk);
                    v[hh * 2 + 1] = *(const float4*)(pX + kk + 4);
                } else if (kk < IS) {
                    float4 s0a = *(const float4*)(pS + kk);
                    float4 s0b = *(const float4*)(pS + kk + 4);
                    if (t == 0) {
                        v[hh * 2 + 0] = s0a;
                        v[hh * 2 + 1] = s0b;
                    } else {
                        float4 s1a = *(const float4*)(pS + SWID + kk);
                        float4 s1b = *(const float4*)(pS + SWID + kk + 4);
                        float4 dva = *(const float4*)(pD + kk);
                        float4 dvb = *(const float4*)(pD + kk + 4);
                        float4 qa, qb;
                        qa.x = cnn * s0a.x + cpu * dva.x + cpo * s1a.x;
                        qa.y = cnn * s0a.y + cpu * dva.y + cpo * s1a.y;
                        qa.z = cnn * s0a.z + cpu * dva.z + cpo * s1a.z;
                        qa.w = cnn * s0a.w + cpu * dva.w + cpo * s1a.w;
                        qb.x = cnn * s0b.x + cpu * dvb.x + cpo * s1b.x;
                        qb.y = cnn * s0b.y + cpu * dvb.y + cpo * s1b.y;
                        qb.z = cnn * s0b.z + cpu * dvb.z + cpo * s1b.z;
                        qb.w = cnn * s0b.w + cpu * dvb.w + cpo * s1b.w;
                        v[hh * 2 + 0] = qa;
                        v[hh * 2 + 1] = qb;
                    }
                } else {
                    v[hh * 2 + 0] = *(const float4*)(pH + kk);
                    v[hh * 2 + 1] = *(const float4*)(pH + kk + 4);
                }
            }
        };
        auto stsA = [&](int buf, const float4 v[4]) {
#pragma unroll
            for (int hh = 0; hh < 2; hh++) {
#pragma unroll
                for (int qh = 0; qh < 2; qh++) {
                    float* p = &sm[buf * BUFSZ + s_base + (hh * 4 + lq) * 132 + 2 * qh];
                    const float4 q = v[hh * 2 + qh];
                    p[0]  = ftf32(q.x);
                    p[4]  = ftf32(q.y);
                    p[8]  = ftf32(q.z);
                    p[12] = ftf32(q.w);
                }
            }
        };
        auto fillB = [&](int kc) {
            const uint32_t dst = bfill_dst + (kc % 3) * 32768;
            const float*   src = bsrc_base + (size_t)kc * 8192;
#pragma unroll
            for (int i = 0; i < 8; i++)
                cpa16(dst + i * 16, src + i * 4);
        };

        // ---- phase 1: gates GEMM, 24 iterations of K=64, warp 32m x 32n ----
        float acc[4][2][4];
#pragma unroll
        for (int g = 0; g < 4; g++)
#pragma unroll
            for (int mf = 0; mf < 2; mf++)
#pragma unroll
                for (int cc = 0; cc < 4; cc++) acc[g][mf][cc] = 0.f;

        float4 vA[4];
        fillB(0); cpa_commit();
        fillB(1); cpa_commit();
        ldgA(0, vA);
        stsA(0, vA);

        for (int kc = 0; kc < 24; kc++) {
            cpa_wait<1>();
            __syncthreads();
            const float* bring = brd_base + (kc % 3) * 8192;
            if (kc + 1 < 24) ldgA(kc + 1, vA);
            const int abase = (kc & 1) * BUFSZ;
#pragma unroll
            for (int hh = 0; hh < 2; hh++) {
                const float4* bp = (const float4*)(bring + hh * 4096 + wn * 1024);
                float4 bb[4][2];
#pragma unroll
                for (int g = 0; g < 4; g++) {
                    bb[g][0] = bp[g * 64 + lane * 2];
                    bb[g][1] = bp[g * 64 + lane * 2 + 1];
                }
#pragma unroll
                for (int ks = 0; ks < 4; ks++) {
                    const int slot = hh * 4 + ks;
                    const float4 af0 = *(const float4*)
                        &sm[abase + ((wm * 2 + 0) * 8 + slot) * 132 + lane * 4];
                    const float4 af1 = *(const float4*)
                        &sm[abase + ((wm * 2 + 1) * 8 + slot) * 132 + lane * 4];
                    uint32_t a0[4] = {__float_as_uint(af0.x), __float_as_uint(af0.y),
                                      __float_as_uint(af0.z), __float_as_uint(af0.w)};
                    uint32_t a1[4] = {__float_as_uint(af1.x), __float_as_uint(af1.y),
                                      __float_as_uint(af1.z), __float_as_uint(af1.w)};
#pragma unroll
                    for (int g = 0; g < 4; g++) {
                        float2 s;
                        if (ks == 0)      s = make_float2(bb[g][0].x, bb[g][0].y);
                        else if (ks == 1) s = make_float2(bb[g][0].z, bb[g][0].w);
                        else if (ks == 2) s = make_float2(bb[g][1].x, bb[g][1].y);
                        else              s = make_float2(bb[g][1].z, bb[g][1].w);
                        uint32_t bf[2] = {__float_as_uint(s.x), __float_as_uint(s.y)};
                        mma_tf32(acc[g][0], a0, bf);
                        mma_tf32(acc[g][1], a1, bf);
                    }
                }
            }
            if (kc + 1 < 24) stsA((kc + 1) & 1, vA);
            if (kc + 2 < 24) fillB(kc + 2);
            cpa_commit();
        }

        // ---- LSTM pointwise epilogue, direct from registers ----
        {
            const int jb = j0 + wn * 8 + (tig << 1);
            const float2 B0 = *(const float2*)(g_bias + jb);
            const float2 B1 = *(const float2*)(g_bias + HID + jb);
            const float2 B2 = *(const float2*)(g_bias + 2 * HID + jb);
            const float2 B3 = *(const float2*)(g_bias + 3 * HID + jb);
#pragma unroll
            for (int mf = 0; mf < 2; mf++) {
#pragma unroll
                for (int cc = 0; cc < 4; cc++) {
                    const int row = wm * 32 + mf * 16 + ((cc >> 1) << 3) + gi_r;
                    const int b = bm0 + row;
                    const int odd = cc & 1;
                    const size_t off = (size_t)b * HID + jb + odd;
                    float gi = acc[0][mf][cc] + (odd ? B0.y : B0.x);
                    float gf = acc[1][mf][cc] + (odd ? B1.y : B1.x);
                    float gg = acc[2][mf][cc] + (odd ? B2.y : B2.x);
                    float go = acc[3][mf][cc] + (odd ? B3.y : B3.x);
                    float iv = 1.f / (1.f + expf(-gi));
                    float fv = 1.f / (1.f + expf(-gf));
                    float gv = tanhf(gg);
                    float ov = 1.f / (1.f + expf(-go));
                    float cn_ = fv * g_c[off] + iv * gv;
                    g_c[off]  = cn_;
                    h_out[off] = ov * tanhf(cn_);
                }
            }
        }

        // ---- barrier A (split): blend overlaps the wait ----
        unsigned myg;
        bar_arrive(&myg);
        blend_range(Sp, So, dprev, ctlprev, t == 0, bid, tid);
        bar_wait(myg);

        // ---- phase 2: d = tanh(h @ D_w^T + D_b); controls softmax ----
        if (bid < 64) {
            const int w0 = (bid & 7) * 32, bm0d = (bid >> 3) * 32;
            const int wm2 = warp >> 2, wn2 = warp & 3;    // 2m x 4n warps of 16x8
            const int HS = 260;
            const int BW = 32 * HS;                       // 8320
            const int lrow = tid >> 3;                    // 0..31
            const int lcol4 = (tid & 7) * 4;
            float acc2[4] = {0.f, 0.f, 0.f, 0.f};
            for (int ch = 0; ch < 4; ch++) {
                __syncthreads();
#pragma unroll
                for (int i = 0; i < 8; i++) {
                    const int col = lcol4 + i * 32;
                    float4 hv = *(const float4*)
                        (h_out + (size_t)(bm0d + lrow) * HID + ch * 256 + col);
                    float* p = &sm[lrow * HS + col];
                    p[0] = ftf32(hv.x); p[1] = ftf32(hv.y);
                    p[2] = ftf32(hv.z); p[3] = ftf32(hv.w);
                    float4 wv = *(const float4*)
                        (D_w + (size_t)(w0 + lrow) * HID + ch * 256 + col);
                    float* q = &sm[BW + lrow * HS + col];
                    q[0] = ftf32(wv.x); q[1] = ftf32(wv.y);
                    q[2] = ftf32(wv.z); q[3] = ftf32(wv.w);
                }
                __syncthreads();
#pragma unroll
                for (int ks = 0; ks < 32; ks++) {
                    const int k0 = ks * 8;
                    uint32_t a[4], bf[2];
                    const int m0 = wm2 * 16;
                    a[0] = __float_as_uint(sm[(m0 + gi_r) * HS + k0 + tig]);
                    a[1] = __float_as_uint(sm[(m0 + 8 + gi_r) * HS + k0 + tig]);
                    a[2] = __float_as_uint(sm[(m0 + gi_r) * HS + k0 + tig + 4]);
                    a[3] = __float_as_uint(sm[(m0 + 8 + gi_r) * HS + k0 + tig + 4]);
                    const int n0 = wn2 * 8;
                    bf[0] = __float_as_uint(sm[BW + (n0 + gi_r) * HS + k0 + tig]);
                    bf[1] = __float_as_uint(sm[BW + (n0 + gi_r) * HS + k0 + tig + 4]);
                    mma_tf32(acc2, a, bf);
                }
            }
#pragma unroll
            for (int cc = 0; cc < 4; cc++) {
                const int row = wm2 * 16 + ((cc >> 1) << 3) + gi_r;
                const int col = wn2 * 8 + (tig << 1) + (cc & 1);
                dcur[(size_t)(bm0d + row) * SWID + w0 + col] =
                    tanhf(acc2[cc] + D_b[w0 + col]);
            }
        } else if (bid < 72) {
            const int bm0c = (bid - 64) * 32;
            for (int q = 0; q < 4; q++) {
                const int b = bm0c + warp * 4 + q;
                float s0 = 0.f, s1 = 0.f, s2 = 0.f;
                for (int k = lane; k < HID; k += 32) {
                    float hv = h_out[(size_t)b * HID + k];
                    s0 += hv * A_w[k];
                    s1 += hv * A_w[HID + k];
                    s2 += hv * A_w[2 * HID + k];
                }
#pragma unroll
                for (int o = 16; o > 0; o >>= 1) {
                    s0 += __shfl_xor_sync(0xffffffffu, s0, o);
                    s1 += __shfl_xor_sync(0xffffffffu, s1, o);
                    s2 += __shfl_xor_sync(0xffffffffu, s2, o);
                }
                if (lane == 0) {
                    s0 += A_b[0]; s1 += A_b[1]; s2 += A_b[2];
                    float mx = fmaxf(s0, fmaxf(s1, s2));
                    float e0 = expf(s0 - mx), e1 = expf(s1 - mx), e2 = expf(s2 - mx);
                    float inv = 1.f / (e0 + e1 + e2);
                    ctlcur[b * 3 + 0] = e0 * inv;
                    ctlcur[b * 3 + 1] = e1 * inv;
                    ctlcur[b * 3 + 2] = e2 * inv;
                }
            }
        }
        gbar();   // d_t / ctl_t visible for step t+1
    }

    // ---- final stack: R_512 = blend(R_511, d_511, ctl_511) -> stackn ----
    blend_range(g_stackA, stackn, g_d + BATCH * SWID, g_ctl + BATCH * 3, 0, bid, tid);
}

// ---------------- launch ----------------
extern "C" void kernel_launch(void* const* d_in, const int* in_sizes, int n_in,
                              void* d_out, int out_size)
{
    const float* x    = (const float*)d_in[0];
    const float* h0   = (const float*)d_in[1];
    const float* c0   = (const float*)d_in[2];
    const float* st0  = (const float*)d_in[3];
    const float* W_ih = (const float*)d_in[4];
    const float* W_hh = (const float*)d_in[5];
    const float* b_ih = (const float*)d_in[6];
    const float* b_hh = (const float*)d_in[7];
    const float* A_w  = (const float*)d_in[8];
    const float* A_b  = (const float*)d_in[9];
    const float* D_w  = (const float*)d_in[10];
    const float* D_b  = (const float*)d_in[11];

    float* out    = (float*)d_out;
    float* outs   = out;
    float* hn     = outs + (size_t)S_LEN * BATCH * HID;
    float* cn     = hn + (size_t)BATCH * HID;
    float* stackn = cn + (size_t)BATCH * HID;

    float *sA, *cbuf;
    cudaGetSymbolAddress((void**)&sA, g_stackA);
    cudaGetSymbolAddress((void**)&cbuf, g_c);

    cudaFuncSetAttribute(stackrnn_persistent,
                         cudaFuncAttributeMaxDynamicSharedMemorySize, DYNSM);

    cudaMemcpyAsync(cbuf, c0, sizeof(float) * BATCH * HID, cudaMemcpyDeviceToDevice);
    cudaMemcpyAsync(sA, st0, sizeof(float) * BATCH * SDEP * SWID, cudaMemcpyDeviceToDevice);

    stackrnn_persistent<<<NB, NT, DYNSM>>>(x, h0, W_ih, W_hh, b_ih, b_hh,
                                           A_w, A_b, D_w, D_b, outs, stackn);

    cudaMemcpyAsync(hn, outs + (size_t)(S_LEN - 1) * BATCH * HID,
                    sizeof(float) * BATCH * HID, cudaMemcpyDeviceToDevice);
    cudaMemcpyAsync(cn, cbuf, sizeof(float) * BATCH * HID, cudaMemcpyDeviceToDevice);
}

// round 12
// speedup vs baseline: 1.0977x; 1.0977x over previous
#include <cuda_runtime.h>
#include <cstdint>
#include <math.h>

#define S_LEN 512
#define BATCH 256
#define IN    256
#define HID   1024
#define SWID  256
#define SDEP  100
#define KTOT  1536
#define IS    (IN + SWID)     // 512
#define NB    128
#define NT    512

#define BUFSZ  4224           // A frag buffer per stage: 4 mt * 8 ks * 132
#define BBASE  (2 * BUFSZ)    // float offset of B ring
#define DYNSM  ((2 * BUFSZ + 3 * 8192) * 4)   // 132096 bytes

// ---------------- scratch (no allocations allowed) ----------------
__device__ __align__(16) float g_stackA[BATCH * SDEP * SWID];   // 26.2 MB
__device__ __align__(16) float g_stackB[BATCH * SDEP * SWID];   // 26.2 MB (also prep staging)
__device__ __align__(16) float g_Wf[32 * 48 * 4096];            // 25.2 MB tile-ordered weights
__device__ __align__(16) float g_xtf[S_LEN * BATCH * IN];       // 134 MB pre-tf32 x
__device__ __align__(16) float g_htf[2 * BATCH * HID];          // 8 MB tf32 h ping-pong
__device__ __align__(16) float g_bias[4 * HID];
__device__ __align__(16) float g_c[BATCH * HID];
__device__ __align__(16) float g_d[2 * BATCH * SWID];
__device__ float g_ctl[2 * BATCH * 3];
__device__ unsigned g_cnt;
__device__ volatile unsigned g_gen;

// ---------------- helpers ----------------
__device__ __forceinline__ float ftf32(float x) {
    float y;
    asm("cvt.rna.tf32.f32 %0, %1;" : "=f"(y) : "f"(x));
    return y;
}
__device__ __forceinline__ uint32_t smem_u32(const void* p) {
    uint32_t a;
    asm("{ .reg .u64 t; cvta.to.shared.u64 t, %1; cvt.u32.u64 %0, t; }" : "=r"(a) : "l"(p));
    return a;
}
__device__ __forceinline__ void cpa16(uint32_t dst, const void* src) {
    asm volatile("cp.async.cg.shared.global [%0], [%1], 16;" :: "r"(dst), "l"(src) : "memory");
}
__device__ __forceinline__ void cpa_commit() { asm volatile("cp.async.commit_group;" ::: "memory"); }
template <int N> __device__ __forceinline__ void cpa_wait() {
    asm volatile("cp.async.wait_group %0;" :: "n"(N) : "memory");
}

__device__ __forceinline__ void mma_tf32(float c[4], const uint32_t a[4], const uint32_t b[2]) {
    asm volatile(
        "mma.sync.aligned.m16n8k8.row.col.f32.tf32.tf32.f32 "
        "{%0,%1,%2,%3}, {%4,%5,%6,%7}, {%8,%9}, {%0,%1,%2,%3};\n"
        : "+f"(c[0]), "+f"(c[1]), "+f"(c[2]), "+f"(c[3])
        : "r"(a[0]), "r"(a[1]), "r"(a[2]), "r"(a[3]), "r"(b[0]), "r"(b[1]));
}

// ---------------- software grid barrier ----------------
__device__ __forceinline__ void gbar() {
    __syncthreads();
    if (threadIdx.x == 0) {
        unsigned my = g_gen;
        __threadfence();
        unsigned a = atomicAdd(&g_cnt, 1u);
        if (a == NB - 1) {
            g_cnt = 0;
            __threadfence();
            g_gen = my + 1;
        }
        while (g_gen == my) { }
        __threadfence();
    }
    __syncthreads();
}

// ---------------- stack blend (final copy, 128-way split) ----------------
__device__ __forceinline__ void blend_range(
    const float* __restrict__ Sp, float* __restrict__ So,
    const float* __restrict__ dbuf, const float* __restrict__ ctlbuf,
    int bid, int tid)
{
    const float4* sin4  = (const float4*)Sp;
    float4*       sout4 = (float4*)So;
    const float4* d4    = (const float4*)dbuf;
    const int per_blk = (BATCH * SDEP * (SWID / 4)) / NB;   // 12800
    for (int ii = tid; ii < per_blk; ii += NT) {
        const int idx = bid * per_blk + ii;
        const int w4   = idx & 63;
        const int jrow = (idx >> 6) % SDEP;
        const int b    = idx / (SDEP * 64);
        const int base = b * SDEP * 64;
        float4 cur = sin4[base + jrow * 64 + w4];
        const float pu = ctlbuf[b * 3 + 0];
        const float po = ctlbuf[b * 3 + 1];
        const float nn = ctlbuf[b * 3 + 2];
        float4 up = (jrow == 0) ? d4[b * 64 + w4] : sin4[base + (jrow - 1) * 64 + w4];
        float4 dn = make_float4(0.f, 0.f, 0.f, 0.f);
        if (jrow < SDEP - 1) dn = sin4[base + (jrow + 1) * 64 + w4];
        float4 o;
        o.x = nn * cur.x + pu * up.x + po * dn.x;
        o.y = nn * cur.y + pu * up.y + po * dn.y;
        o.z = nn * cur.z + pu * up.z + po * dn.z;
        o.w = nn * cur.w + pu * up.w + po * dn.w;
        sout4[idx] = o;
    }
}

// ---------------- in-loop blend: grid-stride over 56 CTAs ----------------
__device__ __forceinline__ void blend_strided(
    const float* __restrict__ Sp, float* __restrict__ So,
    const float* __restrict__ dbuf, const float* __restrict__ ctlbuf,
    int is_t0, int start, int stride)
{
    const float4* sin4  = (const float4*)Sp;
    float4*       sout4 = (float4*)So;
    const float4* d4    = (const float4*)dbuf;
    const int total4 = BATCH * SDEP * (SWID / 4);   // 1,638,400
    for (int idx = start; idx < total4; idx += stride) {
        const int w4   = idx & 63;
        const int jrow = (idx >> 6) % SDEP;
        const int b    = idx / (SDEP * 64);
        const int base = b * SDEP * 64;
        float4 cur = sin4[base + jrow * 64 + w4];
        float4 o;
        if (is_t0) {
            o = cur;
        } else {
            const float pu = ctlbuf[b * 3 + 0];
            const float po = ctlbuf[b * 3 + 1];
            const float nn = ctlbuf[b * 3 + 2];
            float4 up = (jrow == 0) ? d4[b * 64 + w4] : sin4[base + (jrow - 1) * 64 + w4];
            float4 dn = make_float4(0.f, 0.f, 0.f, 0.f);
            if (jrow < SDEP - 1) dn = sin4[base + (jrow + 1) * 64 + w4];
            o.x = nn * cur.x + pu * up.x + po * dn.x;
            o.y = nn * cur.y + pu * up.y + po * dn.y;
            o.z = nn * cur.z + pu * up.z + po * dn.z;
            o.w = nn * cur.w + pu * up.w + po * dn.w;
        }
        sout4[idx] = o;
    }
}

// ---------------- the persistent kernel (prep + 512 steps) ----------------
__global__ __launch_bounds__(NT) void stackrnn_persistent(
    const float* __restrict__ x,      // [S, B, IN]
    const float* __restrict__ h0,
    const float* __restrict__ W_ih,   // [4H, IS]
    const float* __restrict__ W_hh,   // [4H, H]
    const float* __restrict__ b_ih,
    const float* __restrict__ b_hh,
    const float* __restrict__ A_w,
    const float* __restrict__ A_b,
    const float* __restrict__ D_w,
    const float* __restrict__ D_b,
    float* __restrict__ outs,         // [S, B, H]
    float* __restrict__ stackn)       // [B, SDEP, SWID]
{
    extern __shared__ __align__(16) float sm[];   // [0,2*BUFSZ) A frags, [BBASE,+3*8192) B ring

    const int bid = blockIdx.x;
    const int tid = threadIdx.x;
    const int warp = tid >> 5, lane = tid & 31;
    const int wm = warp >> 2, wn = warp & 3;        // 4m x 4n warps (phase 1)
    const int gi_r = lane >> 2, tig = lane & 3;
    const int jt = bid & 31, mt = bid >> 5, bm0 = mt * 64;
    const int j0 = jt * 32;

    // ======== prep P0/P1: tf32 x, h0, plain weights -> g_stackB, fused bias ========
    for (int idx = bid * NT + tid; idx < S_LEN * BATCH * IN; idx += NB * NT)
        g_xtf[idx] = ftf32(x[idx]);
    for (int idx = bid * NT + tid; idx < BATCH * HID; idx += NB * NT)
        g_htf[BATCH * HID + idx] = ftf32(h0[idx]);   // slot 1 = h at t=0 read
    for (int idx = bid * NT + tid; idx < 4 * HID * KTOT; idx += NB * NT) {
        int row = idx / KTOT, k = idx - row * KTOT;
        float v = (k < IS) ? W_ih[(size_t)row * IS + k]
                           : W_hh[(size_t)row * HID + (k - IS)];
        g_stackB[idx] = ftf32(v);
    }
    for (int i = bid * NT + tid; i < 4 * HID; i += NB * NT)
        g_bias[i] = b_ih[i] + b_hh[i];
    gbar();
    // ======== prep P2: tile-order swizzle -> g_Wf ========
    for (int idx = bid * NT + tid; idx < 32 * 48 * 4096; idx += NB * NT) {
        int w    = idx & 7;
        int ln   = (idx >> 3) & 31;
        int g    = (idx >> 8) & 3;
        int wnn  = (idx >> 10) & 3;
        int kc   = (idx >> 12) % 48;
        int jtt  = idx / (48 * 4096);
        int row = g * HID + jtt * 32 + wnn * 8 + (ln >> 2);
        int k   = kc * 32 + (w >> 1) * 8 + (ln & 3) + 4 * (w & 1);
        g_Wf[idx] = g_stackB[(size_t)row * KTOT + k];
    }
    gbar();

    // A loader role: thread -> row lr (0..63), k-offset lk within 64-chunk halves
    const int lr = tid >> 3;            // 0..63
    const int lk = (tid & 7) << 2;      // 0,4,...,28
    const int lb = bm0 + lr;
    // frag-scatter constants (8 ks slots per stage)
    const int s_mt  = lr >> 4;
    const int s_gid = lr & 7;
    const int s_hi  = (lr >> 3) & 1;
    const int s_ks  = lk >> 3;
    const int s_q   = (lk >> 2) & 1;
    const int s_w   = s_hi + 2 * s_q;
    const int s_off = (s_mt * 8 + s_ks) * 132 + (s_gid * 4) * 4 + s_w;
    // B fill/read bases
    const uint32_t smem_base = smem_u32(sm);
    const uint32_t bfill_dst = smem_base + BBASE * 4 + tid * 64;
    const float*   bsrc_base = g_Wf + (size_t)jt * 48 * 4096 + tid * 16;
    const float*   brd_base  = sm + BBASE + wn * 1024 + lane * 8;

    for (int t = 0; t < S_LEN; t++) {
        float*       h_out  = outs + (size_t)t * BATCH * HID;
        const float* Sp = (t & 1) ? g_stackB : g_stackA;
        float*       So = (t & 1) ? g_stackA : g_stackB;
        const float* dprev   = g_d   + ((t + 1) & 1) * (BATCH * SWID);
        const float* ctlprev = g_ctl + ((t + 1) & 1) * (BATCH * 3);
        float*       dcur    = g_d   + (t & 1) * (BATCH * SWID);
        float*       ctlcur  = g_ctl + (t & 1) * (BATCH * 3);
        const int rslot = (t & 1) ^ 1;                // g_htf read slot
        float*       htf_w  = g_htf + (t & 1) * (BATCH * HID);

        float cpu = 0.f, cpo = 0.f, cnn = 1.f;
        if (t) {
            cpu = ctlprev[lb * 3 + 0];
            cpo = ctlprev[lb * 3 + 1];
            cnn = ctlprev[lb * 3 + 2];
        }
        const float* pX = g_xtf + (size_t)t * BATCH * IN + (size_t)lb * IN + lk;
        const float* pS = Sp + (size_t)lb * (SDEP * SWID) + lk - IN;
        const float* pD = dprev + (size_t)lb * SWID + lk - IN;
        const float* pH = g_htf + (size_t)rslot * BATCH * HID + (size_t)lb * HID + lk - IS;

        // kc64 regions: x = kc 0..3, stack = kc 4..7, h = kc 8..23
        auto ldgA = [&](int kc, float4 v[2]) {
#pragma unroll
            for (int hh = 0; hh < 2; hh++) {
                const int kk = kc * 64 + hh * 32 + lk;
                if (kk < IN) {
                    v[hh] = *(const float4*)(pX + kk - lk);
                } else if (kk < IS) {
                    float4 s0 = *(const float4*)(pS + kk - lk);
                    float4 q;
                    if (t == 0) {
                        q.x = ftf32(s0.x); q.y = ftf32(s0.y);
                        q.z = ftf32(s0.z); q.w = ftf32(s0.w);
                    } else {
                        float4 s1 = *(const float4*)(pS + SWID + kk - lk);
                        float4 dv = *(const float4*)(pD + kk - lk);
                        q.x = ftf32(cnn * s0.x + cpu * dv.x + cpo * s1.x);
                        q.y = ftf32(cnn * s0.y + cpu * dv.y + cpo * s1.y);
                        q.z = ftf32(cnn * s0.z + cpu * dv.z + cpo * s1.z);
                        q.w = ftf32(cnn * s0.w + cpu * dv.w + cpo * s1.w);
                    }
                    v[hh] = q;
                } else {
                    v[hh] = *(const float4*)(pH + kk - lk);
                }
            }
        };
        auto stsA = [&](int buf, const float4 v[2]) {
#pragma unroll
            for (int hh = 0; hh < 2; hh++) {
                float* p = &sm[buf * BUFSZ + s_off + hh * (4 * 132)];
                p[0]  = v[hh].x;
                p[4]  = v[hh].y;
                p[8]  = v[hh].z;
                p[12] = v[hh].w;
            }
        };
        auto fillB = [&](int kc) {
            const uint32_t dst = bfill_dst + (kc % 3) * 32768;
            const float*   src = bsrc_base + (size_t)kc * 8192;
            cpa16(dst,      src);
            cpa16(dst + 16, src + 4);
            cpa16(dst + 32, src + 8);
            cpa16(dst + 48, src + 12);
        };

        // ---- phase 1: gates GEMM, 24 iterations of K=64 ----
        float acc[4][4];
#pragma unroll
        for (int g = 0; g < 4; g++)
#pragma unroll
            for (int cc = 0; cc < 4; cc++) acc[g][cc] = 0.f;

        float4 vA[2];
        fillB(0); cpa_commit();
        fillB(1); cpa_commit();
        ldgA(0, vA);
        stsA(0, vA);

        for (int kc = 0; kc < 24; kc++) {
            cpa_wait<1>();
            __syncthreads();
            const float* bring = brd_base + (kc % 3) * 8192;
            if (kc + 1 < 24) ldgA(kc + 1, vA);
#pragma unroll
            for (int hh = 0; hh < 2; hh++) {
                const float4* bp = (const float4*)(bring + hh * 4096);
                float4 bb[4][2];
#pragma unroll
                for (int g = 0; g < 4; g++) {
                    bb[g][0] = bp[g * 64 + 0];
                    bb[g][1] = bp[g * 64 + 1];
                }
#pragma unroll
                for (int ks = 0; ks < 4; ks++) {
                    const float4 af = *(const float4*)
                        &sm[(kc & 1) * BUFSZ + (wm * 8 + hh * 4 + ks) * 132 + lane * 4];
                    uint32_t a[4] = {__float_as_uint(af.x), __float_as_uint(af.y),
                                     __float_as_uint(af.z), __float_as_uint(af.w)};
#pragma unroll
                    for (int g = 0; g < 4; g++) {
                        float2 s;
                        if (ks == 0)      s = make_float2(bb[g][0].x, bb[g][0].y);
                        else if (ks == 1) s = make_float2(bb[g][0].z, bb[g][0].w);
                        else if (ks == 2) s = make_float2(bb[g][1].x, bb[g][1].y);
                        else              s = make_float2(bb[g][1].z, bb[g][1].w);
                        uint32_t bf[2] = {__float_as_uint(s.x), __float_as_uint(s.y)};
                        mma_tf32(acc[g], a, bf);
                    }
                }
            }
            if (kc + 1 < 24) stsA((kc + 1) & 1, vA);
            if (kc + 2 < 24) fillB(kc + 2);
            cpa_commit();
        }

        // ---- LSTM pointwise epilogue: write h (exact) + h_tf (tf32) ----
        {
            const int jb = j0 + wn * 8 + (tig << 1);
            const float2 B0 = *(const float2*)(g_bias + jb);
            const float2 B1 = *(const float2*)(g_bias + HID + jb);
            const float2 B2 = *(const float2*)(g_bias + 2 * HID + jb);
            const float2 B3 = *(const float2*)(g_bias + 3 * HID + jb);
#pragma unroll
            for (int cc = 0; cc < 4; cc++) {
                const int row = wm * 16 + ((cc >> 1) << 3) + gi_r;
                const int b = bm0 + row;
                const int odd = cc & 1;
                const size_t off = (size_t)b * HID + jb + odd;
                float gi = acc[0][cc] + (odd ? B0.y : B0.x);
                float gf = acc[1][cc] + (odd ? B1.y : B1.x);
                float gg = acc[2][cc] + (odd ? B2.y : B2.x);
                float go = acc[3][cc] + (odd ? B3.y : B3.x);
                float iv = 1.f / (1.f + expf(-gi));
                float fv = 1.f / (1.f + expf(-gf));
                float gv = tanhf(gg);
                float ov = 1.f / (1.f + expf(-go));
                float cn_ = fv * g_c[off] + iv * gv;
                g_c[off]  = cn_;
                float hv = ov * tanhf(cn_);
                h_out[off] = hv;
                htf_w[off] = ftf32(hv);
            }
        }

        gbar();   // h_t complete everywhere

        // ---- phase 2 slot: d-GEMM (0..63) | softmax (64..71) | blend (72..127) ----
        if (bid < 64) {
            const int w0 = (bid & 7) * 32, bm0d = (bid >> 3) * 32;
            const int mi = warp >> 3;            // 0..1
            const int ni = (warp >> 1) & 3;      // 0..3
            const int kh = warp & 1;             // 0..1 (k-split)
            const int HS = 260;
            const int BW = 32 * HS;              // 8320
            const int RED = 2 * BW;              // 16640
            const int lrow = tid >> 4;           // 0..31
            const int lcol = (tid & 15) * 4;
            float acc2[4] = {0.f, 0.f, 0.f, 0.f};
            for (int ch = 0; ch < 4; ch++) {
                __syncthreads();
#pragma unroll
                for (int i = 0; i < 4; i++) {
                    const int col = lcol + i * 64;
                    float4 hv = *(const float4*)
                        (h_out + (size_t)(bm0d + lrow) * HID + ch * 256 + col);
                    float* p = &sm[lrow * HS + col];
                    p[0] = ftf32(hv.x); p[1] = ftf32(hv.y);
                    p[2] = ftf32(hv.z); p[3] = ftf32(hv.w);
                    float4 wv = *(const float4*)
                        (D_w + (size_t)(w0 + lrow) * HID + ch * 256 + col);
                    float* q = &sm[BW + lrow * HS + col];
                    q[0] = ftf32(wv.x); q[1] = ftf32(wv.y);
                    q[2] = ftf32(wv.z); q[3] = ftf32(wv.w);
                }
                __syncthreads();
#pragma unroll
                for (int ks = 0; ks < 16; ks++) {
                    const int k0 = (kh * 16 + ks) * 8;
                    uint32_t a[4], bf[2];
                    const int m0 = mi * 16;
                    a[0] = __float_as_uint(sm[(m0 + gi_r) * HS + k0 + tig]);
                    a[1] = __float_as_uint(sm[(m0 + 8 + gi_r) * HS + k0 + tig]);
                    a[2] = __float_as_uint(sm[(m0 + gi_r) * HS + k0 + tig + 4]);
                    a[3] = __float_as_uint(sm[(m0 + 8 + gi_r) * HS + k0 + tig + 4]);
                    const int n0 = ni * 8;
                    bf[0] = __float_as_uint(sm[BW + (n0 + gi_r) * HS + k0 + tig]);
                    bf[1] = __float_as_uint(sm[BW + (n0 + gi_r) * HS + k0 + tig + 4]);
                    mma_tf32(acc2, a, bf);
                }
            }
            __syncthreads();
            if (kh == 1) {
                float* p = &sm[RED + ((mi * 4 + ni) * 32 + lane) * 4];
                p[0] = acc2[0]; p[1] = acc2[1]; p[2] = acc2[2]; p[3] = acc2[3];
            }
            __syncthreads();
            if (kh == 0) {
                const float* p = &sm[RED + ((mi * 4 + ni) * 32 + lane) * 4];
#pragma unroll
                for (int cc = 0; cc < 4; cc++) {
                    const int row = mi * 16 + ((cc >> 1) << 3) + gi_r;
                    const int col = ni * 8 + (tig << 1) + (cc & 1);
                    dcur[(size_t)(bm0d + row) * SWID + w0 + col] =
                        tanhf(acc2[cc] + p[cc] + D_b[w0 + col]);
                }
            }
        } else if (bid < 72) {
            const int bm0c = (bid - 64) * 32;
            for (int q = 0; q < 2; q++) {
                const int b = bm0c + warp * 2 + q;
                float s0 = 0.f, s1 = 0.f, s2 = 0.f;
                for (int k = lane; k < HID; k += 32) {
                    float hv = h_out[(size_t)b * HID + k];
                    s0 += hv * A_w[k];
                    s1 += hv * A_w[HID + k];
                    s2 += hv * A_w[2 * HID + k];
                }
#pragma unroll
                for (int o = 16; o > 0; o >>= 1) {
                    s0 += __shfl_xor_sync(0xffffffffu, s0, o);
                    s1 += __shfl_xor_sync(0xffffffffu, s1, o);
                    s2 += __shfl_xor_sync(0xffffffffu, s2, o);
                }
                if (lane == 0) {
                    s0 += A_b[0]; s1 += A_b[1]; s2 += A_b[2];
                    float mx = fmaxf(s0, fmaxf(s1, s2));
                    float e0 = expf(s0 - mx), e1 = expf(s1 - mx), e2 = expf(s2 - mx);
                    float inv = 1.f / (e0 + e1 + e2);
                    ctlcur[b * 3 + 0] = e0 * inv;
                    ctlcur[b * 3 + 1] = e1 * inv;
                    ctlcur[b * 3 + 2] = e2 * inv;
                }
            }
        } else {
            // blend R_t = blend(R_{t-1}, d_{t-1}, ctl_{t-1}) on 56 CTAs
            blend_strided(Sp, So, dprev, ctlprev, t == 0,
                          (bid - 72) * NT + tid, 56 * NT);
        }
        gbar();   // d_t / ctl_t / R_t visible for step t+1
    }

    // ---- final stack: R_512 = blend(R_511, d_511, ctl_511) -> stackn ----
    blend_range(g_stackA, stackn, g_d + BATCH * SWID, g_ctl + BATCH * 3, bid, tid);
}

// ---------------- launch ----------------
extern "C" void kernel_launch(void* const* d_in, const int* in_sizes, int n_in,
                              void* d_out, int out_size)
{
    const float* x    = (const float*)d_in[0];
    const float* h0   = (const float*)d_in[1];
    const float* c0   = (const float*)d_in[2];
    const float* st0  = (const float*)d_in[3];
    const float* W_ih = (const float*)d_in[4];
    const float* W_hh = (const float*)d_in[5];
    const float* b_ih = (const float*)d_in[6];
    const float* b_hh = (const float*)d_in[7];
    const float* A_w  = (const float*)d_in[8];
    const float* A_b  = (const float*)d_in[9];
    const float* D_w  = (const float*)d_in[10];
    const float* D_b  = (const float*)d_in[11];

    float* out    = (float*)d_out;
    float* outs   = out;
    float* hn     = outs + (size_t)S_LEN * BATCH * HID;
    float* cn     = hn + (size_t)BATCH * HID;
    float* stackn = cn + (size_t)BATCH * HID;

    float *sA, *cbuf;
    cudaGetSymbolAddress((void**)&sA, g_stackA);
    cudaGetSymbolAddress((void**)&cbuf, g_c);

    cudaFuncSetAttribute(stackrnn_persistent,
                         cudaFuncAttributeMaxDynamicSharedMemorySize, DYNSM);

    cudaMemcpyAsync(cbuf, c0, sizeof(float) * BATCH * HID, cudaMemcpyDeviceToDevice);
    cudaMemcpyAsync(sA, st0, sizeof(float) * BATCH * SDEP * SWID, cudaMemcpyDeviceToDevice);

    stackrnn_persistent<<<NB, NT, DYNSM>>>(x, h0, W_ih, W_hh, b_ih, b_hh,
                                           A_w, A_b, D_w, D_b, outs, stackn);

    cudaMemcpyAsync(hn, outs + (size_t)(S_LEN - 1) * BATCH * HID,
                    sizeof(float) * BATCH * HID, cudaMemcpyDeviceToDevice);
    cudaMemcpyAsync(cn, cbuf, sizeof(float) * BATCH * HID, cudaMemcpyDeviceToDevice);
}

// round 13
// speedup vs baseline: 1.2909x; 1.1760x over previous
#include <cuda_runtime.h>
#include <cstdint>
#include <math.h>

#define S_LEN 512
#define BATCH 256
#define IN    256
#define HID   1024
#define SWID  256
#define SDEP  100
#define KTOT  1536
#define IS    (IN + SWID)     // 512
#define NB    128
#define NT    512

#define BUFSZ  4224           // A frag buffer per stage: 4 mt * 8 ks * 132
#define BBASE  (2 * BUFSZ)    // float offset of B ring
#define DYNSM  ((2 * BUFSZ + 3 * 8192) * 4)   // 132096 bytes

// ---------------- scratch (no allocations allowed) ----------------
__device__ __align__(16) float g_stackA[BATCH * SDEP * SWID];   // 26.2 MB
__device__ __align__(16) float g_stackB[BATCH * SDEP * SWID];   // 26.2 MB (also prep staging)
__device__ __align__(16) float g_Wf[32 * 48 * 4096];            // 25.2 MB tile-ordered weights
__device__ __align__(16) float g_xtf[S_LEN * BATCH * IN];       // 134 MB pre-tf32 x
__device__ __align__(16) float g_htf[2 * BATCH * HID];          // 8 MB tf32 h ping-pong
__device__ __align__(16) float g_bias[4 * HID];
__device__ __align__(16) float g_c[BATCH * HID];
__device__ __align__(16) float g_d[2 * BATCH * SWID];
__device__ float g_ctl[2 * BATCH * 3];
__device__ unsigned g_cnt;
__device__ volatile unsigned g_gen;

// ---------------- helpers ----------------
__device__ __forceinline__ float ftf32(float x) {
    float y;
    asm("cvt.rna.tf32.f32 %0, %1;" : "=f"(y) : "f"(x));
    return y;
}
__device__ __forceinline__ uint32_t smem_u32(const void* p) {
    uint32_t a;
    asm("{ .reg .u64 t; cvta.to.shared.u64 t, %1; cvt.u32.u64 %0, t; }" : "=r"(a) : "l"(p));
    return a;
}
__device__ __forceinline__ void cpa16(uint32_t dst, const void* src) {
    asm volatile("cp.async.cg.shared.global [%0], [%1], 16;" :: "r"(dst), "l"(src) : "memory");
}
__device__ __forceinline__ void cpa_commit() { asm volatile("cp.async.commit_group;" ::: "memory"); }
template <int N> __device__ __forceinline__ void cpa_wait() {
    asm volatile("cp.async.wait_group %0;" :: "n"(N) : "memory");
}

__device__ __forceinline__ void mma_tf32(float c[4], const uint32_t a[4], const uint32_t b[2]) {
    asm volatile(
        "mma.sync.aligned.m16n8k8.row.col.f32.tf32.tf32.f32 "
        "{%0,%1,%2,%3}, {%4,%5,%6,%7}, {%8,%9}, {%0,%1,%2,%3};\n"
        : "+f"(c[0]), "+f"(c[1]), "+f"(c[2]), "+f"(c[3])
        : "r"(a[0]), "r"(a[1]), "r"(a[2]), "r"(a[3]), "r"(b[0]), "r"(b[1]));
}

// ---------------- software grid barrier ----------------
__device__ __forceinline__ void bar_arrive(unsigned* myGen) {
    __syncthreads();
    if (threadIdx.x == 0) {
        unsigned my = g_gen;
        __threadfence();
        unsigned a = atomicAdd(&g_cnt, 1u);
        if (a == NB - 1) {
            g_cnt = 0;
            __threadfence();
            g_gen = my + 1;
        }
        *myGen = my;
    }
}
__device__ __forceinline__ void bar_wait(unsigned myGen) {
    if (threadIdx.x == 0) {
        while (g_gen == myGen) { }
        __threadfence();
    }
    __syncthreads();
}
__device__ __forceinline__ void gbar() {
    unsigned m;
    bar_arrive(&m);
    bar_wait(m);
}

// ---------------- stack blend (1/128 per CTA) ----------------
__device__ __forceinline__ void blend_range(
    const float* __restrict__ Sp, float* __restrict__ So,
    const float* __restrict__ dbuf, const float* __restrict__ ctlbuf,
    int is_t0, int bid, int tid)
{
    const float4* sin4  = (const float4*)Sp;
    float4*       sout4 = (float4*)So;
    const float4* d4    = (const float4*)dbuf;
    const int per_blk = (BATCH * SDEP * (SWID / 4)) / NB;   // 12800
    for (int ii = tid; ii < per_blk; ii += NT) {
        const int idx = bid * per_blk + ii;
        const int w4   = idx & 63;
        const int jrow = (idx >> 6) % SDEP;
        const int b    = idx / (SDEP * 64);
        const int base = b * SDEP * 64;
        float4 cur = sin4[base + jrow * 64 + w4];
        float4 o;
        if (is_t0) {
            o = cur;
        } else {
            const float pu = ctlbuf[b * 3 + 0];
            const float po = ctlbuf[b * 3 + 1];
            const float nn = ctlbuf[b * 3 + 2];
            float4 up = (jrow == 0) ? d4[b * 64 + w4] : sin4[base + (jrow - 1) * 64 + w4];
            float4 dn = make_float4(0.f, 0.f, 0.f, 0.f);
            if (jrow < SDEP - 1) dn = sin4[base + (jrow + 1) * 64 + w4];
            o.x = nn * cur.x + pu * up.x + po * dn.x;
            o.y = nn * cur.y + pu * up.y + po * dn.y;
            o.z = nn * cur.z + pu * up.z + po * dn.z;
            o.w = nn * cur.w + pu * up.w + po * dn.w;
        }
        sout4[idx] = o;
    }
}

// ---------------- the persistent kernel (prep + 512 steps) ----------------
__global__ __launch_bounds__(NT) void stackrnn_persistent(
    const float* __restrict__ x,      // [S, B, IN]
    const float* __restrict__ h0,
    const float* __restrict__ W_ih,   // [4H, IS]
    const float* __restrict__ W_hh,   // [4H, H]
    const float* __restrict__ b_ih,
    const float* __restrict__ b_hh,
    const float* __restrict__ A_w,
    const float* __restrict__ A_b,
    const float* __restrict__ D_w,
    const float* __restrict__ D_b,
    float* __restrict__ outs,         // [S, B, H]
    float* __restrict__ stackn)       // [B, SDEP, SWID]
{
    extern __shared__ __align__(16) float sm[];   // [0,2*BUFSZ) A frags, [BBASE,+3*8192) B ring

    const int bid = blockIdx.x;
    const int tid = threadIdx.x;
    const int warp = tid >> 5, lane = tid & 31;
    const int wm = warp >> 2, wn = warp & 3;        // 4m x 4n warps (phase 1)
    const int gi_r = lane >> 2, tig = lane & 3;
    const int jt = bid & 31, mt = bid >> 5, bm0 = mt * 64;
    const int j0 = jt * 32;

    // ======== prep P0/P1: tf32 x, h0; plain tf32 weights -> g_stackB; bias ========
    for (int idx = bid * NT + tid; idx < S_LEN * BATCH * IN; idx += NB * NT)
        g_xtf[idx] = ftf32(x[idx]);
    for (int idx = bid * NT + tid; idx < BATCH * HID; idx += NB * NT)
        g_htf[BATCH * HID + idx] = ftf32(h0[idx]);   // slot 1 = h read at t=0
    for (int idx = bid * NT + tid; idx < 4 * HID * KTOT; idx += NB * NT) {
        int row = idx / KTOT, k = idx - row * KTOT;
        float v = (k < IS) ? W_ih[(size_t)row * IS + k]
                           : W_hh[(size_t)row * HID + (k - IS)];
        g_stackB[idx] = ftf32(v);
    }
    for (int i = bid * NT + tid; i < 4 * HID; i += NB * NT)
        g_bias[i] = b_ih[i] + b_hh[i];
    gbar();
    // ======== prep P2: tile-order swizzle -> g_Wf ========
    for (int idx = bid * NT + tid; idx < 32 * 48 * 4096; idx += NB * NT) {
        int w    = idx & 7;
        int ln   = (idx >> 3) & 31;
        int g    = (idx >> 8) & 3;
        int wnn  = (idx >> 10) & 3;
        int kc   = (idx >> 12) % 48;
        int jtt  = idx / (48 * 4096);
        int row = g * HID + jtt * 32 + wnn * 8 + (ln >> 2);
        int k   = kc * 32 + (w >> 1) * 8 + (ln & 3) + 4 * (w & 1);
        g_Wf[idx] = g_stackB[(size_t)row * KTOT + k];
    }
    gbar();

    // A loader role: thread -> row lr (0..63), k-offset lk within 64-chunk halves
    const int lr = tid >> 3;            // 0..63
    const int lk = (tid & 7) << 2;      // 0,4,...,28
    const int lb = bm0 + lr;
    // frag-scatter constants (8 ks slots per stage)
    const int s_mt  = lr >> 4;
    const int s_gid = lr & 7;
    const int s_hi  = (lr >> 3) & 1;
    const int s_ks  = lk >> 3;
    const int s_q   = (lk >> 2) & 1;
    const int s_w   = s_hi + 2 * s_q;
    const int s_off = (s_mt * 8 + s_ks) * 132 + (s_gid * 4) * 4 + s_w;
    // B fill/read bases
    const uint32_t smem_base = smem_u32(sm);
    const uint32_t bfill_dst = smem_base + BBASE * 4 + tid * 64;
    const float*   bsrc_base = g_Wf + (size_t)jt * 48 * 4096 + tid * 16;
    const float*   brd_base  = sm + BBASE + wn * 1024 + lane * 8;

    for (int t = 0; t < S_LEN; t++) {
        float*       h_out  = outs + (size_t)t * BATCH * HID;
        const float* Sp = (t & 1) ? g_stackB : g_stackA;
        float*       So = (t & 1) ? g_stackA : g_stackB;
        const float* dprev   = g_d   + ((t + 1) & 1) * (BATCH * SWID);
        const float* ctlprev = g_ctl + ((t + 1) & 1) * (BATCH * 3);
        float*       dcur    = g_d   + (t & 1) * (BATCH * SWID);
        float*       ctlcur  = g_ctl + (t & 1) * (BATCH * 3);
        const int rslot = (t & 1) ^ 1;
        float*       htf_w  = g_htf + (t & 1) * (BATCH * HID);

        float cpu = 0.f, cpo = 0.f, cnn = 1.f;
        if (t) {
            cpu = ctlprev[lb * 3 + 0];
            cpo = ctlprev[lb * 3 + 1];
            cnn = ctlprev[lb * 3 + 2];
        }
        const float* pX = g_xtf + (size_t)t * BATCH * IN + (size_t)lb * IN + lk;
        const float* pS = Sp + (size_t)lb * (SDEP * SWID) + lk - IN;
        const float* pD = dprev + (size_t)lb * SWID + lk - IN;
        const float* pH = g_htf + (size_t)rslot * BATCH * HID + (size_t)lb * HID + lk - IS;

        // kc64 regions: x = kc 0..3, stack = kc 4..7, h = kc 8..23
        auto ldgA = [&](int kc, float4 v[2]) {
#pragma unroll
            for (int hh = 0; hh < 2; hh++) {
                const int kk = kc * 64 + hh * 32 + lk;
                if (kk < IN) {
                    v[hh] = *(const float4*)(pX + kk - lk);
                } else if (kk < IS) {
                    float4 s0 = *(const float4*)(pS + kk - lk);
                    float4 q;
                    if (t == 0) {
                        q.x = ftf32(s0.x); q.y = ftf32(s0.y);
                        q.z = ftf32(s0.z); q.w = ftf32(s0.w);
                    } else {
                        float4 s1 = *(const float4*)(pS + SWID + kk - lk);
                        float4 dv = *(const float4*)(pD + kk - lk);
                        q.x = ftf32(cnn * s0.x + cpu * dv.x + cpo * s1.x);
                        q.y = ftf32(cnn * s0.y + cpu * dv.y + cpo * s1.y);
                        q.z = ftf32(cnn * s0.z + cpu * dv.z + cpo * s1.z);
                        q.w = ftf32(cnn * s0.w + cpu * dv.w + cpo * s1.w);
                    }
                    v[hh] = q;
                } else {
                    v[hh] = *(const float4*)(pH + kk - lk);
                }
            }
        };
        auto stsA = [&](int buf, const float4 v[2]) {
#pragma unroll
            for (int hh = 0; hh < 2; hh++) {
                float* p = &sm[buf * BUFSZ + s_off + hh * (4 * 132)];
                p[0]  = v[hh].x;
                p[4]  = v[hh].y;
                p[8]  = v[hh].z;
                p[12] = v[hh].w;
            }
        };
        auto fillB = [&](int kc) {
            const uint32_t dst = bfill_dst + (kc % 3) * 32768;
            const float*   src = bsrc_base + (size_t)kc * 8192;
            cpa16(dst,      src);
            cpa16(dst + 16, src + 4);
            cpa16(dst + 32, src + 8);
            cpa16(dst + 48, src + 12);
        };

        // ---- phase 1: gates GEMM, 24 iterations of K=64 ----
        float acc[4][4];
#pragma unroll
        for (int g = 0; g < 4; g++)
#pragma unroll
            for (int cc = 0; cc < 4; cc++) acc[g][cc] = 0.f;

        float4 vA[2];
        fillB(0); cpa_commit();
        fillB(1); cpa_commit();
        ldgA(0, vA);
        stsA(0, vA);

        for (int kc = 0; kc < 24; kc++) {
            cpa_wait<1>();
            __syncthreads();
            const float* bring = brd_base + (kc % 3) * 8192;
            if (kc + 1 < 24) ldgA(kc + 1, vA);
#pragma unroll
            for (int hh = 0; hh < 2; hh++) {
                const float4* bp = (const float4*)(bring + hh * 4096);
                float4 bb[4][2];
#pragma unroll
                for (int g = 0; g < 4; g++) {
                    bb[g][0] = bp[g * 64 + 0];
                    bb[g][1] = bp[g * 64 + 1];
                }
#pragma unroll
                for (int ks = 0; ks < 4; ks++) {
                    const float4 af = *(const float4*)
                        &sm[(kc & 1) * BUFSZ + (wm * 8 + hh * 4 + ks) * 132 + lane * 4];
                    uint32_t a[4] = {__float_as_uint(af.x), __float_as_uint(af.y),
                                     __float_as_uint(af.z), __float_as_uint(af.w)};
#pragma unroll
                    for (int g = 0; g < 4; g++) {
                        float2 s;
                        if (ks == 0)      s = make_float2(bb[g][0].x, bb[g][0].y);
                        else if (ks == 1) s = make_float2(bb[g][0].z, bb[g][0].w);
                        else if (ks == 2) s = make_float2(bb[g][1].x, bb[g][1].y);
                        else              s = make_float2(bb[g][1].z, bb[g][1].w);
                        uint32_t bf[2] = {__float_as_uint(s.x), __float_as_uint(s.y)};
                        mma_tf32(acc[g], a, bf);
                    }
                }
            }
            if (kc + 1 < 24) stsA((kc + 1) & 1, vA);
            if (kc + 2 < 24) fillB(kc + 2);
            cpa_commit();
        }

        // ---- LSTM pointwise epilogue: write h (exact) + h_tf (tf32) ----
        {
            const int jb = j0 + wn * 8 + (tig << 1);
            const float2 B0 = *(const float2*)(g_bias + jb);
            const float2 B1 = *(const float2*)(g_bias + HID + jb);
            const float2 B2 = *(const float2*)(g_bias + 2 * HID + jb);
            const float2 B3 = *(const float2*)(g_bias + 3 * HID + jb);
#pragma unroll
            for (int cc = 0; cc < 4; cc++) {
                const int row = wm * 16 + ((cc >> 1) << 3) + gi_r;
                const int b = bm0 + row;
                const int odd = cc & 1;
                const size_t off = (size_t)b * HID + jb + odd;
                float gi = acc[0][cc] + (odd ? B0.y : B0.x);
                float gf = acc[1][cc] + (odd ? B1.y : B1.x);
                float gg = acc[2][cc] + (odd ? B2.y : B2.x);
                float go = acc[3][cc] + (odd ? B3.y : B3.x);
                float iv = 1.f / (1.f + expf(-gi));
                float fv = 1.f / (1.f + expf(-gf));
                float gv = tanhf(gg);
                float ov = 1.f / (1.f + expf(-go));
                float cn_ = fv * g_c[off] + iv * gv;
                g_c[off]  = cn_;
                float hv = ov * tanhf(cn_);
                h_out[off] = hv;
                htf_w[off] = ftf32(hv);
            }
        }

        // ---- barrier A (split): blend overlaps the wait ----
        unsigned myg;
        bar_arrive(&myg);
        blend_range(Sp, So, dprev, ctlprev, t == 0, bid, tid);
        bar_wait(myg);

        // ---- phase 2: d = tanh(h @ D_w^T + D_b); controls softmax ----
        if (bid < 64) {
            const int w0 = (bid & 7) * 32, bm0d = (bid >> 3) * 32;
            const int mi = warp >> 3;            // 0..1
            const int ni = (warp >> 1) & 3;      // 0..3
            const int kh = warp & 1;             // 0..1 (k-split)
            const int HS = 260;
            const int BW = 32 * HS;              // 8320
            const int RED = 2 * BW;              // 16640
            const int lrow = tid >> 4;           // 0..31
            const int lcol = (tid & 15) * 4;
            float acc2[4] = {0.f, 0.f, 0.f, 0.f};
            for (int ch = 0; ch < 4; ch++) {
                __syncthreads();
#pragma unroll
                for (int i = 0; i < 4; i++) {
                    const int col = lcol + i * 64;
                    float4 hv = *(const float4*)
                        (h_out + (size_t)(bm0d + lrow) * HID + ch * 256 + col);
                    float* p = &sm[lrow * HS + col];
                    p[0] = ftf32(hv.x); p[1] = ftf32(hv.y);
                    p[2] = ftf32(hv.z); p[3] = ftf32(hv.w);
                    float4 wv = *(const float4*)
                        (D_w + (size_t)(w0 + lrow) * HID + ch * 256 + col);
                    float* q = &sm[BW + lrow * HS + col];
                    q[0] = ftf32(wv.x); q[1] = ftf32(wv.y);
                    q[2] = ftf32(wv.z); q[3] = ftf32(wv.w);
                }
                __syncthreads();
#pragma unroll
                for (int ks = 0; ks < 16; ks++) {
                    const int k0 = (kh * 16 + ks) * 8;
                    uint32_t a[4], bf[2];
                    const int m0 = mi * 16;
                    a[0] = __float_as_uint(sm[(m0 + gi_r) * HS + k0 + tig]);
                    a[1] = __float_as_uint(sm[(m0 + 8 + gi_r) * HS + k0 + tig]);
                    a[2] = __float_as_uint(sm[(m0 + gi_r) * HS + k0 + tig + 4]);
                    a[3] = __float_as_uint(sm[(m0 + 8 + gi_r) * HS + k0 + tig + 4]);
                    const int n0 = ni * 8;
                    bf[0] = __float_as_uint(sm[BW + (n0 + gi_r) * HS + k0 + tig]);
                    bf[1] = __float_as_uint(sm[BW + (n0 + gi_r) * HS + k0 + tig + 4]);
                    mma_tf32(acc2, a, bf);
                }
            }
            __syncthreads();
            if (kh == 1) {
                float* p = &sm[RED + ((mi * 4 + ni) * 32 + lane) * 4];
                p[0] = acc2[0]; p[1] = acc2[1]; p[2] = acc2[2]; p[3] = acc2[3];
            }
            __syncthreads();
            if (kh == 0) {
                const float* p = &sm[RED + ((mi * 4 + ni) * 32 + lane) * 4];
#pragma unroll
                for (int cc = 0; cc < 4; cc++) {
                    const int row = mi * 16 + ((cc >> 1) << 3) + gi_r;
                    const int col = ni * 8 + (tig << 1) + (cc & 1);
                    dcur[(size_t)(bm0d + row) * SWID + w0 + col] =
                        tanhf(acc2[cc] + p[cc] + D_b[w0 + col]);
                }
            }
        } else if (bid < 72) {
            const int bm0c = (bid - 64) * 32;
            for (int q = 0; q < 2; q++) {
                const int b = bm0c + warp * 2 + q;
                float s0 = 0.f, s1 = 0.f, s2 = 0.f;
                for (int k = lane; k < HID; k += 32) {
                    float hv = h_out[(size_t)b * HID + k];
                    s0 += hv * A_w[k];
                    s1 += hv * A_w[HID + k];
                    s2 += hv * A_w[2 * HID + k];
                }
#pragma unroll
                for (int o = 16; o > 0; o >>= 1) {
                    s0 += __shfl_xor_sync(0xffffffffu, s0, o);
                    s1 += __shfl_xor_sync(0xffffffffu, s1, o);
                    s2 += __shfl_xor_sync(0xffffffffu, s2, o);
                }
                if (lane == 0) {
                    s0 += A_b[0]; s1 += A_b[1]; s2 += A_b[2];
                    float mx = fmaxf(s0, fmaxf(s1, s2));
                    float e0 = expf(s0 - mx), e1 = expf(s1 - mx), e2 = expf(s2 - mx);
                    float inv = 1.f / (e0 + e1 + e2);
                    ctlcur[b * 3 + 0] = e0 * inv;
                    ctlcur[b * 3 + 1] = e1 * inv;
                    ctlcur[b * 3 + 2] = e2 * inv;
                }
            }
        }
        gbar();   // d_t / ctl_t visible for step t+1
    }

    // ---- final stack: R_512 = blend(R_511, d_511, ctl_511) -> stackn ----
    blend_range(g_stackA, stackn, g_d + BATCH * SWID, g_ctl + BATCH * 3, 0, bid, tid);
}

// ---------------- launch ----------------
extern "C" void kernel_launch(void* const* d_in, const int* in_sizes, int n_in,
                              void* d_out, int out_size)
{
    const float* x    = (const float*)d_in[0];
    const float* h0   = (const float*)d_in[1];
    const float* c0   = (const float*)d_in[2];
    const float* st0  = (const float*)d_in[3];
    const float* W_ih = (const float*)d_in[4];
    const float* W_hh = (const float*)d_in[5];
    const float* b_ih = (const float*)d_in[6];
    const float* b_hh = (const float*)d_in[7];
    const float* A_w  = (const float*)d_in[8];
    const float* A_b  = (const float*)d_in[9];
    const float* D_w  = (const float*)d_in[10];
    const float* D_b  = (const float*)d_in[11];

    float* out    = (float*)d_out;
    float* outs   = out;
    float* hn     = outs + (size_t)S_LEN * BATCH * HID;
    float* cn     = hn + (size_t)BATCH * HID;
    float* stackn = cn + (size_t)BATCH * HID;

    float *sA, *cbuf;
    cudaGetSymbolAddress((void**)&sA, g_stackA);
    cudaGetSymbolAddress((void**)&cbuf, g_c);

    cudaFuncSetAttribute(stackrnn_persistent,
                         cudaFuncAttributeMaxDynamicSharedMemorySize, DYNSM);

    cudaMemcpyAsync(cbuf, c0, sizeof(float) * BATCH * HID, cudaMemcpyDeviceToDevice);
    cudaMemcpyAsync(sA, st0, sizeof(float) * BATCH * SDEP * SWID, cudaMemcpyDeviceToDevice);

    stackrnn_persistent<<<NB, NT, DYNSM>>>(x, h0, W_ih, W_hh, b_ih, b_hh,
                                           A_w, A_b, D_w, D_b, outs, stackn);

    cudaMemcpyAsync(hn, outs + (size_t)(S_LEN - 1) * BATCH * HID,
                    sizeof(float) * BATCH * HID, cudaMemcpyDeviceToDevice);
    cudaMemcpyAsync(cn, cbuf, sizeof(float) * BATCH * HID, cudaMemcpyDeviceToDevice);
}

// round 16
// speedup vs baseline: 2.4281x; 1.8809x over previous
#include <cuda_runtime.h>
#include <cuda_fp16.h>
#include <cstdint>
#include <math.h>

#define S_LEN 512
#define BATCH 256
#define IN    256
#define HID   1024
#define SWID  256
#define SDEP  100
#define KTOT  1536
#define IS    (IN + SWID)     // 512
#define NB    128
#define NT    512

#define ABUF   2112           // A frag stage: 4 mt * 4 slot * 132 u32 (fp16 pairs)
#define BRING  (2 * ABUF)     // u32 offset of B ring (3 x 4096 u32)
#define DYNSM  70656          // bytes: max(66048 GEMM, 70656 phase2 incl. RED region)

// ---------------- scratch (no allocations allowed) ----------------
__device__ __align__(16) float    g_stackA[BATCH * SDEP * SWID];   // 26.2 MB
__device__ __align__(16) float    g_stackB[BATCH * SDEP * SWID];   // 26.2 MB (+ prep staging)
__device__ __align__(16) uint32_t g_Wfh[32 * 24 * 4096];           // 12.6 MB fp16 tile weights
__device__ __align__(16) uint32_t g_xh[S_LEN * BATCH * IN / 2];    // 67 MB fp16 x
__device__ __align__(16) uint32_t g_hh[2 * BATCH * HID / 2];       // 1 MB fp16 h ping-pong
__device__ __align__(16) float    g_bias[4 * HID];
__device__ __align__(16) float    g_c[BATCH * HID];
__device__ __align__(16) float    g_d[2 * BATCH * SWID];
__device__ float g_ctl[2 * BATCH * 3];
__device__ unsigned g_cnt;
__device__ volatile unsigned g_gen;

// ---------------- helpers ----------------
__device__ __forceinline__ float ftf32(float x) {
    float y;
    asm("cvt.rna.tf32.f32 %0, %1;" : "=f"(y) : "f"(x));
    return y;
}
__device__ __forceinline__ uint32_t f2h2(float a, float b) {
    __half2 h = __floats2half2_rn(a, b);
    return *(uint32_t*)&h;
}
__device__ __forceinline__ uint32_t smem_u32(const void* p) {
    uint32_t a;
    asm("{ .reg .u64 t; cvta.to.shared.u64 t, %1; cvt.u32.u64 %0, t; }" : "=r"(a) : "l"(p));
    return a;
}
__device__ __forceinline__ void cpa16(uint32_t dst, const void* src) {
    asm volatile("cp.async.cg.shared.global [%0], [%1], 16;" :: "r"(dst), "l"(src) : "memory");
}
__device__ __forceinline__ void cpa_commit() { asm volatile("cp.async.commit_group;" ::: "memory"); }
template <int N> __device__ __forceinline__ void cpa_wait() {
    asm volatile("cp.async.wait_group %0;" :: "n"(N) : "memory");
}

__device__ __forceinline__ void mma_f16(float c[4], const uint32_t a[4], const uint32_t b[2]) {
    asm volatile(
        "mma.sync.aligned.m16n8k16.row.col.f32.f16.f16.f32 "
        "{%0,%1,%2,%3}, {%4,%5,%6,%7}, {%8,%9}, {%0,%1,%2,%3};\n"
        : "+f"(c[0]), "+f"(c[1]), "+f"(c[2]), "+f"(c[3])
        : "r"(a[0]), "r"(a[1]), "r"(a[2]), "r"(a[3]), "r"(b[0]), "r"(b[1]));
}
__device__ __forceinline__ void mma_tf32(float c[4], const uint32_t a[4], const uint32_t b[2]) {
    asm volatile(
        "mma.sync.aligned.m16n8k8.row.col.f32.tf32.tf32.f32 "
        "{%0,%1,%2,%3}, {%4,%5,%6,%7}, {%8,%9}, {%0,%1,%2,%3};\n"
        : "+f"(c[0]), "+f"(c[1]), "+f"(c[2]), "+f"(c[3])
        : "r"(a[0]), "r"(a[1]), "r"(a[2]), "r"(a[3]), "r"(b[0]), "r"(b[1]));
}

// ---------------- software grid barrier ----------------
__device__ __forceinline__ void bar_arrive(unsigned* myGen) {
    __syncthreads();
    if (threadIdx.x == 0) {
        unsigned my = g_gen;
        __threadfence();
        unsigned a = atomicAdd(&g_cnt, 1u);
        if (a == NB - 1) {
            g_cnt = 0;
            __threadfence();
            g_gen = my + 1;
        }
        *myGen = my;
    }
}
__device__ __forceinline__ void bar_wait(unsigned myGen) {
    if (threadIdx.x == 0) {
        while (g_gen == myGen) { }
        __threadfence();
    }
    __syncthreads();
}
__device__ __forceinline__ void gbar() {
    unsigned m;
    bar_arrive(&m);
    bar_wait(m);
}

// ---------------- stack blend (1/128 per CTA) ----------------
__device__ __forceinline__ void blend_range(
    const float* __restrict__ Sp, float* __restrict__ So,
    const float* __restrict__ dbuf, const float* __restrict__ ctlbuf,
    int is_t0, int bid, int tid)
{
    const float4* sin4  = (const float4*)Sp;
    float4*       sout4 = (float4*)So;
    const float4* d4    = (const float4*)dbuf;
    const int per_blk = (BATCH * SDEP * (SWID / 4)) / NB;   // 12800
    for (int ii = tid; ii < per_blk; ii += NT) {
        const int idx = bid * per_blk + ii;
        const int w4   = idx & 63;
        const int jrow = (idx >> 6) % SDEP;
        const int b    = idx / (SDEP * 64);
        const int base = b * SDEP * 64;
        float4 cur = sin4[base + jrow * 64 + w4];
        float4 o;
        if (is_t0) {
            o = cur;
        } else {
            const float pu = ctlbuf[b * 3 + 0];
            const float po = ctlbuf[b * 3 + 1];
            const float nn = ctlbuf[b * 3 + 2];
            float4 up = (jrow == 0) ? d4[b * 64 + w4] : sin4[base + (jrow - 1) * 64 + w4];
            float4 dn = make_float4(0.f, 0.f, 0.f, 0.f);
            if (jrow < SDEP - 1) dn = sin4[base + (jrow + 1) * 64 + w4];
            o.x = nn * cur.x + pu * up.x + po * dn.x;
            o.y = nn * cur.y + pu * up.y + po * dn.y;
            o.z = nn * cur.z + pu * up.z + po * dn.z;
            o.w = nn * cur.w + pu * up.w + po * dn.w;
        }
        sout4[idx] = o;
    }
}

// ---------------- the persistent kernel (prep + 512 steps) ----------------
__global__ __launch_bounds__(NT) void stackrnn_persistent(
    const float* __restrict__ x,      // [S, B, IN]
    const float* __restrict__ h0,
    const float* __restrict__ W_ih,   // [4H, IS]
    const float* __restrict__ W_hh,   // [4H, H]
    const float* __restrict__ b_ih,
    const float* __restrict__ b_hh,
    const float* __restrict__ A_w,
    const float* __restrict__ A_b,
    const float* __restrict__ D_w,
    const float* __restrict__ D_b,
    float* __restrict__ outs,         // [S, B, H]
    float* __restrict__ stackn)       // [B, SDEP, SWID]
{
    extern __shared__ __align__(16) float sm[];
    uint32_t* smu = (uint32_t*)sm;    // GEMM view: [0,2*ABUF) A, [BRING,+3*4096) B

    const int bid = blockIdx.x;
    const int tid = threadIdx.x;
    const int warp = tid >> 5, lane = tid & 31;
    const int wm = warp >> 2, wn = warp & 3;        // 4m x 4n warps (phase 1)
    const int gi_r = lane >> 2, tig = lane & 3;
    const int jt = bid & 31, mt = bid >> 5, bm0 = mt * 64;
    const int j0 = jt * 32;

    // ======== prep P0: fp16 x and h0 ========
    for (int i = bid * NT + tid; i < S_LEN * BATCH * IN / 4; i += NB * NT) {
        float4 v = ((const float4*)x)[i];
        g_xh[2 * i]     = f2h2(v.x, v.y);
        g_xh[2 * i + 1] = f2h2(v.z, v.w);
    }
    for (int i = bid * NT + tid; i < BATCH * HID / 4; i += NB * NT) {
        float4 v = ((const float4*)h0)[i];
        g_hh[131072 + 2 * i]     = f2h2(v.x, v.y);
        g_hh[131072 + 2 * i + 1] = f2h2(v.z, v.w);
    }
    // ======== prep P1: plain fp32 weights -> g_stackB; fused bias ========
    for (int idx = bid * NT + tid; idx < 4 * HID * KTOT; idx += NB * NT) {
        int row = idx / KTOT, k = idx - row * KTOT;
        g_stackB[idx] = (k < IS) ? W_ih[(size_t)row * IS + k]
                                 : W_hh[(size_t)row * HID + (k - IS)];
    }
    for (int i = bid * NT + tid; i < 4 * HID; i += NB * NT)
        g_bias[i] = b_ih[i] + b_hh[i];
    gbar();
    // ======== prep P2: fp16 tile-order swizzle -> g_Wfh ========
    // granule (jt, kc64) 4096 u32: pos = (wn*4+s)*256 + q*128 + lane*4 + (g&1)*2 + reg
    for (int idx = bid * NT + tid; idx < 32 * 24 * 4096; idx += NB * NT) {
        int reg = idx & 1;
        int gq  = (idx >> 1) & 1;
        int ln  = (idx >> 2) & 31;
        int q   = (idx >> 7) & 1;
        int s   = (idx >> 8) & 3;
        int wnn = (idx >> 10) & 3;
        int kc  = (idx >> 12) % 24;
        int jtt = idx / (24 * 4096);
        int g   = q * 2 + gq;
        int row = g * HID + jtt * 32 + wnn * 8 + (ln >> 2);
        int k0  = kc * 64 + (s * 8 + (ln & 3) + reg * 4) * 2;
        const float* wp = g_stackB + (size_t)row * KTOT + k0;
        g_Wfh[idx] = f2h2(wp[0], wp[1]);
    }
    gbar();

    // A producer role: thread -> row lr (0..63), k-granule kq (8 fp16)
    const int lr = tid >> 3;
    const int kq = tid & 7;
    const int lk = kq << 3;
    const int lb = bm0 + lr;
    const int s_base = ((lr >> 4) * 4 + (kq >> 1)) * 132 + (lr & 7) * 16
                       + ((lr >> 3) & 1) + 2 * (kq & 1);
    // B fill bases
    const uint32_t smem_base = smem_u32(sm);
    const uint32_t bfill_dst = smem_base + BRING * 4 + tid * 32;
    const uint32_t* bsrc = g_Wfh + (size_t)jt * 24 * 4096 + tid * 8;

    for (int t = 0; t < S_LEN; t++) {
        float*       h_out  = outs + (size_t)t * BATCH * HID;
        const float* Sp = (t & 1) ? g_stackB : g_stackA;
        float*       So = (t & 1) ? g_stackA : g_stackB;
        const float* dprev   = g_d   + ((t + 1) & 1) * (BATCH * SWID);
        const float* ctlprev = g_ctl + ((t + 1) & 1) * (BATCH * 3);
        float*       dcur    = g_d   + (t & 1) * (BATCH * SWID);
        float*       ctlcur  = g_ctl + (t & 1) * (BATCH * 3);
        const int    rslot   = (t & 1) ^ 1;
        uint32_t*    hh_w    = g_hh + (t & 1) * 131072;

        float cpu = 0.f, cpo = 0.f, cnn = 1.f;
        if (t) {
            cpu = ctlprev[lb * 3 + 0];
            cpo = ctlprev[lb * 3 + 1];
            cnn = ctlprev[lb * 3 + 2];
        }
        const uint32_t* pX = g_xh + (size_t)t * 32768 + lb * 128 + kq * 4;
        const float*    pSb = Sp + (size_t)lb * (SDEP * SWID);
        const float*    pDb = dprev + (size_t)lb * SWID;
        const uint32_t* pH = g_hh + (size_t)rslot * 131072 + lb * 512 + kq * 4;

        // kc64 regions: x = kc 0..3, stack = kc 4..7, h = kc 8..23
        auto ldgA = [&](int kc) -> uint4 {
            const int k = kc * 64 + lk;
            if (k < IN) {
                return *(const uint4*)(pX + kc * 32);
            } else if (k < IS) {
                const int w = k - IN;
                float4 s0a = *(const float4*)(pSb + w);
                float4 s0b = *(const float4*)(pSb + w + 4);
                uint4 u;
                if (t == 0) {
                    u.x = f2h2(s0a.x, s0a.y); u.y = f2h2(s0a.z, s0a.w);
                    u.z = f2h2(s0b.x, s0b.y); u.w = f2h2(s0b.z, s0b.w);
                } else {
                    float4 s1a = *(const float4*)(pSb + SWID + w);
                    float4 s1b = *(const float4*)(pSb + SWID + w + 4);
                    float4 dva = *(const float4*)(pDb + w);
                    float4 dvb = *(const float4*)(pDb + w + 4);
                    float r0 = cnn * s0a.x + cpu * dva.x + cpo * s1a.x;
                    float r1 = cnn * s0a.y + cpu * dva.y + cpo * s1a.y;
                    float r2 = cnn * s0a.z + cpu * dva.z + cpo * s1a.z;
                    float r3 = cnn * s0a.w + cpu * dva.w + cpo * s1a.w;
                    float r4 = cnn * s0b.x + cpu * dvb.x + cpo * s1b.x;
                    float r5 = cnn * s0b.y + cpu * dvb.y + cpo * s1b.y;
                    float r6 = cnn * s0b.z + cpu * dvb.z + cpo * s1b.z;
                    float r7 = cnn * s0b.w + cpu * dvb.w + cpo * s1b.w;
                    u.x = f2h2(r0, r1); u.y = f2h2(r2, r3);
                    u.z = f2h2(r4, r5); u.w = f2h2(r6, r7);
                }
                return u;
            } else {
                return *(const uint4*)(pH + (kc - 8) * 32);
            }
        };
        auto stsA = [&](int buf, uint4 v) {
            uint32_t* p = smu + buf * ABUF + s_base;
            p[0]  = v.x;
            p[4]  = v.y;
            p[8]  = v.z;
            p[12] = v.w;
        };
        auto fillB = [&](int kc) {
            const uint32_t dst = bfill_dst + (kc % 3) * 16384;
            const uint32_t* src = bsrc + (size_t)kc * 4096;
            cpa16(dst,      src);
            cpa16(dst + 16, src + 4);
        };

        // ---- phase 1: gates GEMM fp16, 24 iterations of K=64 ----
        float acc[4][4];
#pragma unroll
        for (int g = 0; g < 4; g++)
#pragma unroll
            for (int cc = 0; cc < 4; cc++) acc[g][cc] = 0.f;

        uint4 vA;
        fillB(0); cpa_commit();
        fillB(1); cpa_commit();
        vA = ldgA(0);
        stsA(0, vA);

        for (int kc = 0; kc < 24; kc++) {
            cpa_wait<1>();
            __syncthreads();
            const uint4* bring4 = (const uint4*)(smu + BRING + (kc % 3) * 4096);
            if (kc + 1 < 24) vA = ldgA(kc + 1);
            const uint32_t* ab = smu + (kc & 1) * ABUF + (wm * 4) * 132;
#pragma unroll
            for (int s = 0; s < 4; s++) {
                uint4 af = *(const uint4*)(ab + s * 132 + lane * 4);
                uint32_t a[4] = {af.x, af.y, af.z, af.w};
                uint4 bA = bring4[(wn * 4 + s) * 64 + lane];
                uint4 bB = bring4[(wn * 4 + s) * 64 + 32 + lane];
                uint32_t b0[2] = {bA.x, bA.y};
                uint32_t b1[2] = {bA.z, bA.w};
                uint32_t b2[2] = {bB.x, bB.y};
                uint32_t b3[2] = {bB.z, bB.w};
                mma_f16(acc[0], a, b0);
                mma_f16(acc[1], a, b1);
                mma_f16(acc[2], a, b2);
                mma_f16(acc[3], a, b3);
            }
            if (kc + 1 < 24) stsA((kc + 1) & 1, vA);
            if (kc + 2 < 24) fillB(kc + 2);
            cpa_commit();
        }

        // ---- LSTM pointwise epilogue: h exact + fp16 copy ----
        {
            const int jb = j0 + wn * 8 + (tig << 1);
            const float2 B0 = *(const float2*)(g_bias + jb);
            const float2 B1 = *(const float2*)(g_bias + HID + jb);
            const float2 B2 = *(const float2*)(g_bias + 2 * HID + jb);
            const float2 B3 = *(const float2*)(g_bias + 3 * HID + jb);
            float HH[4];
#pragma unroll
            for (int cc = 0; cc < 4; cc++) {
                const int row = wm * 16 + ((cc >> 1) << 3) + gi_r;
                const int b = bm0 + row;
                const int odd = cc & 1;
                const size_t off = (size_t)b * HID + jb + odd;
                float gi = acc[0][cc] + (odd ? B0.y : B0.x);
                float gf = acc[1][cc] + (odd ? B1.y : B1.x);
                float gg = acc[2][cc] + (odd ? B2.y : B2.x);
                float go = acc[3][cc] + (odd ? B3.y : B3.x);
                float iv = 1.f / (1.f + expf(-gi));
                float fv = 1.f / (1.f + expf(-gf));
                float gv = tanhf(gg);
                float ov = 1.f / (1.f + expf(-go));
                float cn_ = fv * g_c[off] + iv * gv;
                g_c[off]  = cn_;
                float hv = ov * tanhf(cn_);
                h_out[off] = hv;
                HH[cc] = hv;
            }
            const int r0 = wm * 16 + gi_r;
            hh_w[((size_t)(bm0 + r0) * HID + jb) >> 1]     = f2h2(HH[0], HH[1]);
            hh_w[((size_t)(bm0 + r0 + 8) * HID + jb) >> 1] = f2h2(HH[2], HH[3]);
        }

        // ---- barrier A (split): blend overlaps the wait ----
        unsigned myg;
        bar_arrive(&myg);
        blend_range(Sp, So, dprev, ctlprev, t == 0, bid, tid);
        bar_wait(myg);

        // ---- phase 2: d = tanh(h @ D_w^T + D_b); controls softmax ----
        if (bid < 64) {
            const int w0 = (bid & 7) * 32, bm0d = (bid >> 3) * 32;
            const int mi = warp >> 3;
            const int ni = (warp >> 1) & 3;
            const int kh = warp & 1;
            const int HS = 260;
            const int BW = 32 * HS;
            const int RED = 2 * BW;
            const int lrow = tid >> 4;
            const int lcol = (tid & 15) * 4;
            float acc2[4] = {0.f, 0.f, 0.f, 0.f};
            for (int ch = 0; ch < 4; ch++) {
                __syncthreads();
#pragma unroll
                for (int i = 0; i < 4; i++) {
                    const int col = lcol + i * 64;
                    float4 hv = *(const float4*)
                        (h_out + (size_t)(bm0d + lrow) * HID + ch * 256 + col);
                    float* p = &sm[lrow * HS + col];
                    p[0] = ftf32(hv.x); p[1] = ftf32(hv.y);
                    p[2] = ftf32(hv.z); p[3] = ftf32(hv.w);
                    float4 wv = *(const float4*)
                        (D_w + (size_t)(w0 + lrow) * HID + ch * 256 + col);
                    float* q = &sm[BW + lrow * HS + col];
                    q[0] = ftf32(wv.x); q[1] = ftf32(wv.y);
                    q[2] = ftf32(wv.z); q[3] = ftf32(wv.w);
                }
                __syncthreads();
#pragma unroll
                for (int ks = 0; ks < 16; ks++) {
                    const int k0 = (kh * 16 + ks) * 8;
                    uint32_t a[4], bf[2];
                    const int m0 = mi * 16;
                    a[0] = __float_as_uint(sm[(m0 + gi_r) * HS + k0 + tig]);
                    a[1] = __float_as_uint(sm[(m0 + 8 + gi_r) * HS + k0 + tig]);
                    a[2] = __float_as_uint(sm[(m0 + gi_r) * HS + k0 + tig + 4]);
                    a[3] = __float_as_uint(sm[(m0 + 8 + gi_r) * HS + k0 + tig + 4]);
                    const int n0 = ni * 8;
                    bf[0] = __float_as_uint(sm[BW + (n0 + gi_r) * HS + k0 + tig]);
                    bf[1] = __float_as_uint(sm[BW + (n0 + gi_r) * HS + k0 + tig + 4]);
                    mma_tf32(acc2, a, bf);
                }
            }
            __syncthreads();
            if (kh == 1) {
                float* p = &sm[RED + ((mi * 4 + ni) * 32 + lane) * 4];
                p[0] = acc2[0]; p[1] = acc2[1]; p[2] = acc2[2]; p[3] = acc2[3];
            }
            __syncthreads();
            if (kh == 0) {
                const float* p = &sm[RED + ((mi * 4 + ni) * 32 + lane) * 4];
#pragma unroll
                for (int cc = 0; cc < 4; cc++) {
                    const int row = mi * 16 + ((cc >> 1) << 3) + gi_r;
                    const int col = ni * 8 + (tig << 1) + (cc & 1);
                    dcur[(size_t)(bm0d + row) * SWID + w0 + col] =
                        tanhf(acc2[cc] + p[cc] + D_b[w0 + col]);
                }
            }
        } else if (bid < 72) {
            const int bm0c = (bid - 64) * 32;
            for (int q = 0; q < 2; q++) {
                const int b = bm0c + warp * 2 + q;
                float s0 = 0.f, s1 = 0.f, s2 = 0.f;
                for (int k = lane; k < HID; k += 32) {
                    float hv = h_out[(size_t)b * HID + k];
                    s0 += hv * A_w[k];
                    s1 += hv * A_w[HID + k];
                    s2 += hv * A_w[2 * HID + k];
                }
#pragma unroll
                for (int o = 16; o > 0; o >>= 1) {
                    s0 += __shfl_xor_sync(0xffffffffu, s0, o);
                    s1 += __shfl_xor_sync(0xffffffffu, s1, o);
                    s2 += __shfl_xor_sync(0xffffffffu, s2, o);
                }
                if (lane == 0) {
                    s0 += A_b[0]; s1 += A_b[1]; s2 += A_b[2];
                    float mx = fmaxf(s0, fmaxf(s1, s2));
                    float e0 = expf(s0 - mx), e1 = expf(s1 - mx), e2 = expf(s2 - mx);
                    float inv = 1.f / (e0 + e1 + e2);
                    ctlcur[b * 3 + 0] = e0 * inv;
                    ctlcur[b * 3 + 1] = e1 * inv;
                    ctlcur[b * 3 + 2] = e2 * inv;
                }
            }
        }
        gbar();   // d_t / ctl_t visible for step t+1
    }

    // ---- final stack: R_512 = blend(R_511, d_511, ctl_511) -> stackn ----
    blend_range(g_stackA, stackn, g_d + BATCH * SWID, g_ctl + BATCH * 3, 0, bid, tid);
}

// ---------------- launch ----------------
extern "C" void kernel_launch(void* const* d_in, const int* in_sizes, int n_in,
                              void* d_out, int out_size)
{
    const float* x    = (const float*)d_in[0];
    const float* h0   = (const float*)d_in[1];
    const float* c0   = (const float*)d_in[2];
    const float* st0  = (const float*)d_in[3];
    const float* W_ih = (const float*)d_in[4];
    const float* W_hh = (const float*)d_in[5];
    const float* b_ih = (const float*)d_in[6];
    const float* b_hh = (const float*)d_in[7];
    const float* A_w  = (const float*)d_in[8];
    const float* A_b  = (const float*)d_in[9];
    const float* D_w  = (const float*)d_in[10];
    const float* D_b  = (const float*)d_in[11];

    float* out    = (float*)d_out;
    float* outs   = out;
    float* hn     = outs + (size_t)S_LEN * BATCH * HID;
    float* cn     = hn + (size_t)BATCH * HID;
    float* stackn = cn + (size_t)BATCH * HID;

    float *sA, *cbuf;
    cudaGetSymbolAddress((void**)&sA, g_stackA);
    cudaGetSymbolAddress((void**)&cbuf, g_c);

    cudaFuncSetAttribute(stackrnn_persistent,
                         cudaFuncAttributeMaxDynamicSharedMemorySize, DYNSM);

    cudaMemcpyAsync(cbuf, c0, sizeof(float) * BATCH * HID, cudaMemcpyDeviceToDevice);
    cudaMemcpyAsync(sA, st0, sizeof(float) * BATCH * SDEP * SWID, cudaMemcpyDeviceToDevice);

    stackrnn_persistent<<<NB, NT, DYNSM>>>(x, h0, W_ih, W_hh, b_ih, b_hh,
                                           A_w, A_b, D_w, D_b, outs, stackn);

    cudaMemcpyAsync(hn, outs + (size_t)(S_LEN - 1) * BATCH * HID,
                    sizeof(float) * BATCH * HID, cudaMemcpyDeviceToDevice);
    cudaMemcpyAsync(cn, cbuf, sizeof(float) * BATCH * HID, cudaMemcpyDeviceToDevice);
}